// round 3
// baseline (speedup 1.0000x reference)
#include <cuda_runtime.h>
#include <math.h>
#include <stdint.h>

// Qwen3 MoE gate: logits = x[T,2048] @ W^T[2048,128]; softmax; top-8; renorm.
// Output (float32): [ topk_idx flattened (T*8) | topk_weight flattened (T*8) ]
//
// Strategy: fused fp32 GEMM + softmax/top-8 epilogue.
//   - 128 blocks x 512 threads; block = 128 tokens x 128 experts (all experts
//     -> epilogue can do top-k locally, no logits round-trip to HBM).
//   - packed fma.rn.f32x2 to reach 128 FMA/SM/cyc (FFMA-3reg is half rate on B300).
//   - register-prefetch double buffering over K (BK=16).

#define HDIM   2048
#define NEXP   128
#define BM     128
#define BK     16
#define NTHR   512
#define TOPK   8

// dynamic smem: mainloop uses 2*BK*128 floats (16KB); epilogue reuses as
// logits [128][129] floats = 66048 B.  Take the max.
#define SMEM_BYTES (BM * (NEXP + 1) * 4)

#define FMA2(c, a, b) asm("fma.rn.f32x2 %0, %1, %2, %0;" : "+l"(c) : "l"(a), "l"(b))
#define PACK2(d, s)   asm("mov.b64 %0, {%1, %1};" : "=l"(d) : "f"(s))
#define UNPACK2(lo, hi, s) asm("mov.b64 {%0, %1}, %2;" : "=f"(lo), "=f"(hi) : "l"(s))

__global__ __launch_bounds__(NTHR, 1)
void gate_kernel(const float* __restrict__ x,
                 const float* __restrict__ w,
                 float* __restrict__ out,
                 int T)
{
    extern __shared__ float smem[];
    float* xs = smem;                 // [BK][BM]  (k-major, transposed)
    float* ws = smem + BK * BM;       // [BK][NEXP]

    const int tid = threadIdx.x;
    const int ty  = tid >> 4;         // 0..31 : row group (4 rows each)
    const int tx  = tid & 15;         // 0..15 : col group (8 cols each)
    const int block_m = blockIdx.x * BM;

    // accumulators: 4 rows x 8 cols as 4x4 packed f32x2 (pairs along N)
    unsigned long long acc[4][4];
#pragma unroll
    for (int i = 0; i < 4; i++)
#pragma unroll
        for (int j = 0; j < 4; j++) acc[i][j] = 0ull;

    // Each thread loads one float4 of x and one float4 of w per K-tile.
    // x tile: 128 rows x 16 floats = 512 float4.  f = tid -> (row, k4).
    const int lm  = tid >> 2;         // 0..127 (token row / expert row)
    const int lk4 = tid & 3;          // 0..3   (float4 within row)
    const float* xg = x + (size_t)(block_m + lm) * HDIM + lk4 * 4;
    const float* wg = w + (size_t)lm * HDIM + lk4 * 4;

    float4 xv = *(const float4*)xg;
    float4 wv = *(const float4*)wg;

    const int ntiles = HDIM / BK;
    for (int kt = 0; kt < ntiles; kt++) {
        __syncthreads();
        // store prefetched tile (transposed)
        xs[(lk4 * 4 + 0) * BM + lm] = xv.x;
        xs[(lk4 * 4 + 1) * BM + lm] = xv.y;
        xs[(lk4 * 4 + 2) * BM + lm] = xv.z;
        xs[(lk4 * 4 + 3) * BM + lm] = xv.w;
        ws[(lk4 * 4 + 0) * NEXP + lm] = wv.x;
        ws[(lk4 * 4 + 1) * NEXP + lm] = wv.y;
        ws[(lk4 * 4 + 2) * NEXP + lm] = wv.z;
        ws[(lk4 * 4 + 3) * NEXP + lm] = wv.w;
        __syncthreads();

        if (kt + 1 < ntiles) {        // prefetch next tile into registers
            xv = *(const float4*)(xg + (kt + 1) * BK);
            wv = *(const float4*)(wg + (kt + 1) * BK);
        }

#pragma unroll
        for (int k = 0; k < BK; k++) {
            // a: 4 consecutive token rows (LDS.128)
            float4 a = *(const float4*)&xs[k * BM + ty * 4];
            // b: 8 consecutive expert cols as 4 packed pairs (2x LDS.128)
            ulonglong2 b01 = *(const ulonglong2*)&ws[k * NEXP + tx * 8];
            ulonglong2 b23 = *(const ulonglong2*)&ws[k * NEXP + tx * 8 + 4];
            unsigned long long a0, a1, a2, a3;
            PACK2(a0, a.x); PACK2(a1, a.y); PACK2(a2, a.z); PACK2(a3, a.w);
            FMA2(acc[0][0], a0, b01.x); FMA2(acc[0][1], a0, b01.y);
            FMA2(acc[0][2], a0, b23.x); FMA2(acc[0][3], a0, b23.y);
            FMA2(acc[1][0], a1, b01.x); FMA2(acc[1][1], a1, b01.y);
            FMA2(acc[1][2], a1, b23.x); FMA2(acc[1][3], a1, b23.y);
            FMA2(acc[2][0], a2, b01.x); FMA2(acc[2][1], a2, b01.y);
            FMA2(acc[2][2], a2, b23.x); FMA2(acc[2][3], a2, b23.y);
            FMA2(acc[3][0], a3, b01.x); FMA2(acc[3][1], a3, b01.y);
            FMA2(acc[3][2], a3, b23.x); FMA2(acc[3][3], a3, b23.y);
        }
    }

    // ---- epilogue: spill logits to smem, then per-token softmax/top-8 ----
    __syncthreads();                       // mainloop smem no longer needed
    float* lg = smem;                      // [BM][NEXP+1] (pad -> conflict-free)
#pragma unroll
    for (int i = 0; i < 4; i++) {
        float* row = lg + (size_t)(ty * 4 + i) * (NEXP + 1) + tx * 8;
#pragma unroll
        for (int j = 0; j < 4; j++) {
            float lo, hi;
            UNPACK2(lo, hi, acc[i][j]);
            row[2 * j]     = lo;
            row[2 * j + 1] = hi;
        }
    }
    __syncthreads();

    if (tid < BM) {
        float* row = lg + (size_t)tid * (NEXP + 1);
        // global max (for stable exp; also equals top-1 value)
        float m0 = row[0];
#pragma unroll 8
        for (int c = 1; c < NEXP; c++) {
            float v = row[c];
            if (v > m0) m0 = v;
        }
        int   ids[TOPK];
        float wts[TOPK];
        float sum = 0.0f;
#pragma unroll
        for (int kk = 0; kk < TOPK; kk++) {
            float best = -INFINITY;
            int   bi   = 0;
#pragma unroll 8
            for (int c = 0; c < NEXP; c++) {
                float v = row[c];
                if (v > best) { best = v; bi = c; }   // ties -> lowest index
            }
            row[bi] = -INFINITY;                       // mark as taken
            ids[kk] = bi;
            float e = expf(best - m0);
            wts[kk] = e;
            sum += e;
        }
        const int token = block_m + tid;
        float* out_idx = out;
        float* out_wt  = out + (size_t)T * TOPK;
#pragma unroll
        for (int kk = 0; kk < TOPK; kk++) {
            out_idx[(size_t)token * TOPK + kk] = (float)ids[kk];
            out_wt [(size_t)token * TOPK + kk] = wts[kk] / sum;
        }
    }
}

extern "C" void kernel_launch(void* const* d_in, const int* in_sizes, int n_in,
                              void* d_out, int out_size)
{
    const float* x = (const float*)d_in[0];   // [4,4096,2048] fp32
    const float* w = (const float*)d_in[1];   // [128,2048]    fp32
    float* out = (float*)d_out;               // [T*8 idx | T*8 weight] fp32

    const int T = in_sizes[0] / HDIM;         // 16384

    cudaFuncSetAttribute(gate_kernel,
                         cudaFuncAttributeMaxDynamicSharedMemorySize,
                         SMEM_BYTES);
    gate_kernel<<<T / BM, NTHR, SMEM_BYTES>>>(x, w, out, T);
}

// round 6
// speedup vs baseline: 3.7712x; 3.7712x over previous
#include <cuda_runtime.h>
#include <cuda_fp16.h>
#include <math.h>
#include <stdint.h>

// Qwen3 MoE gate via 3-pass split-FP16 mma.sync (compute_103-safe: no tcgen05).
// logit = xh*wh + 2^-11*(xl_s*wh + xh*wl_s),  xl_s = fp16((x-xh)*2048), etc.
// Fused softmax/top-8/renorm epilogue. Output: [idx f32 (T*8) | weights (T*8)].

#define HDIM 2048
#define NEXP 128
#define BM   128
#define BK   64                   // fp16 elements per K-chunk (128B rows)
#define NCH  (HDIM / BK)          // 32
#define NTHR 512
#define TOPK 8

#define TILE_B   (128 * 128)      // 16KB: one operand tile (128 rows x 128B)
#define OFF_XH   0
#define OFF_XL   TILE_B
#define OFF_WH   (2 * TILE_B)
#define OFF_WL   (3 * TILE_B)
#define STAGE_B  (4 * TILE_B)     // 64KB per stage
#define SMEM_TOT (2 * STAGE_B)    // 128KB (epilogue logits 66KB reuses this)

__device__ __half g_wh[NEXP * HDIM];
__device__ __half g_wl[NEXP * HDIM];

__device__ __forceinline__ uint32_t smem_u32(const void* p) {
    uint32_t a;
    asm("{ .reg .u64 t; cvta.to.shared.u64 t, %1; cvt.u32.u64 %0, t; }"
        : "=r"(a) : "l"(p));
    return a;
}

#define SWZ(o) ((o) ^ ((((uint32_t)(o)) >> 3) & 0x70))

#define CP16(dst, src) \
    asm volatile("cp.async.cg.shared.global [%0], [%1], 16;" \
                 :: "r"(dst), "l"(src))
#define CP_COMMIT() asm volatile("cp.async.commit_group;" ::: "memory")
#define CP_WAIT0()  asm volatile("cp.async.wait_group 0;" ::: "memory")

#define LDM4(R, a) \
    asm volatile("ldmatrix.sync.aligned.m8n8.x4.shared.b16 {%0,%1,%2,%3}, [%4];" \
                 : "=r"((R)[0]), "=r"((R)[1]), "=r"((R)[2]), "=r"((R)[3])      \
                 : "r"(a))

#define MMA(d, a, b0, b1) \
    asm volatile("mma.sync.aligned.m16n8k16.row.col.f32.f16.f16.f32 "          \
                 "{%0,%1,%2,%3}, {%4,%5,%6,%7}, {%8,%9}, {%0,%1,%2,%3};"       \
                 : "+f"((d)[0]), "+f"((d)[1]), "+f"((d)[2]), "+f"((d)[3])      \
                 : "r"((a)[0]), "r"((a)[1]), "r"((a)[2]), "r"((a)[3]),         \
                   "r"(b0), "r"(b1))

__device__ __forceinline__ uint32_t pack_h2(float a, float b) {
    __half2 h = __floats2half2_rn(a, b);
    return *(uint32_t*)&h;
}

// -------- prep: split W into fp16 hi + (lo * 2048) --------
__global__ void prep_w_kernel(const float* __restrict__ w) {
    int i = blockIdx.x * blockDim.x + threadIdx.x;      // float4 index
    float4 v = ((const float4*)w)[i];
    float hx = __half2float(__float2half_rn(v.x));
    float hy = __half2float(__float2half_rn(v.y));
    float hz = __half2float(__float2half_rn(v.z));
    float hw = __half2float(__float2half_rn(v.w));
    uint2 hi, lo;
    hi.x = pack_h2(hx, hy);
    hi.y = pack_h2(hz, hw);
    lo.x = pack_h2((v.x - hx) * 2048.0f, (v.y - hy) * 2048.0f);
    lo.y = pack_h2((v.z - hz) * 2048.0f, (v.w - hw) * 2048.0f);
    ((uint2*)g_wh)[i] = hi;
    ((uint2*)g_wl)[i] = lo;
}

// -------- main fused kernel --------
__global__ __launch_bounds__(NTHR, 1)
void gate_kernel(const float* __restrict__ x, float* __restrict__ out, int T)
{
    extern __shared__ char smem[];
    const uint32_t sb = smem_u32(smem);
    const int tid  = threadIdx.x;
    const int lane = tid & 31;
    const int wid  = tid >> 5;
    const int bm   = blockIdx.x * BM;

    // accumulators: [mt][nt][4]  (pass1, and combined correction passes)
    float acc1[2][4][4], acc2[2][4][4];
#pragma unroll
    for (int i = 0; i < 2; i++)
#pragma unroll
        for (int j = 0; j < 4; j++)
#pragma unroll
            for (int r = 0; r < 4; r++) { acc1[i][j][r] = 0.f; acc2[i][j][r] = 0.f; }

    // x loader: 4 float4 per thread per chunk
    const int xrow[4] = { (tid + 0*NTHR) >> 4, (tid + 1*NTHR) >> 4,
                          (tid + 2*NTHR) >> 4, (tid + 3*NTHR) >> 4 };
    const int xq = tid & 15;
    const float* xg = x + (size_t)bm * HDIM;

    // W cp.async loader: 2 x 16B lines per operand per thread
    const int wrow[2] = { (tid + 0*NTHR) >> 3, (tid + 1*NTHR) >> 3 };
    const int ws = tid & 7;

    // warp tiling: 4x4 warps, warp tile 32(M) x 32(N)
    const int wm = (wid & 3) * 32;
    const int wn = (wid >> 2) * 32;
    // ldmatrix lane address components
    const int aRow = (lane & 7) + ((lane >> 3) & 1) * 8;   // + mt*16
    const int aKB  = ((lane >> 4) & 1) * 16;               // k-half bytes
    const int bRow = (lane & 7) + ((lane >> 4) & 1) * 8;   // + p*16
    const int bKB  = ((lane >> 3) & 1) * 16;

#define ISSUE_W(c, stg) do {                                                   \
    _Pragma("unroll")                                                          \
    for (int j = 0; j < 2; j++) {                                              \
        uint32_t o  = SWZ((uint32_t)(wrow[j] * 128 + ws * 16));                \
        const __half* sh = g_wh + (size_t)wrow[j] * HDIM + (c) * BK + ws * 8;  \
        const __half* sl = g_wl + (size_t)wrow[j] * HDIM + (c) * BK + ws * 8;  \
        CP16(sb + (stg) + OFF_WH + o, sh);                                     \
        CP16(sb + (stg) + OFF_WL + o, sl);                                     \
    }                                                                          \
    CP_COMMIT();                                                               \
} while (0)

#define LOAD_X(c, xr) do {                                                     \
    _Pragma("unroll")                                                          \
    for (int j = 0; j < 4; j++)                                                \
        xr[j] = *(const float4*)(xg + (size_t)xrow[j] * HDIM + (c) * BK + xq * 4); \
} while (0)

#define STORE_X(xr, stg) do {                                                  \
    _Pragma("unroll")                                                          \
    for (int j = 0; j < 4; j++) {                                              \
        float4 v = xr[j];                                                      \
        float hx = __half2float(__float2half_rn(v.x));                         \
        float hy = __half2float(__float2half_rn(v.y));                         \
        float hz = __half2float(__float2half_rn(v.z));                         \
        float hw = __half2float(__float2half_rn(v.w));                         \
        uint2 hi, lo;                                                          \
        hi.x = pack_h2(hx, hy);  hi.y = pack_h2(hz, hw);                       \
        lo.x = pack_h2((v.x - hx) * 2048.f, (v.y - hy) * 2048.f);              \
        lo.y = pack_h2((v.z - hz) * 2048.f, (v.w - hw) * 2048.f);              \
        uint32_t o = SWZ((uint32_t)(xrow[j] * 128 + xq * 8));                  \
        *(uint2*)(smem + (stg) + OFF_XH + o) = hi;                             \
        *(uint2*)(smem + (stg) + OFF_XL + o) = lo;                             \
    }                                                                          \
} while (0)

    // ---- prologue: chunk 0 into stage 0 ----
    {
        float4 xr[4];
        ISSUE_W(0, 0);
        LOAD_X(0, xr);
        STORE_X(xr, 0);
        CP_WAIT0();
        __syncthreads();
    }

    // ---- main loop ----
    for (int c = 0; c < NCH; c++) {
        const uint32_t stg  = (uint32_t)((c & 1) ? STAGE_B : 0);
        const uint32_t nstg = stg ^ STAGE_B;
        float4 xr[4];
        if (c + 1 < NCH) {
            ISSUE_W(c + 1, nstg);
            LOAD_X(c + 1, xr);
        }

        // MMA on stage `stg`
#pragma unroll
        for (int ks = 0; ks < 4; ks++) {
            uint32_t Ah[2][4], Al[2][4], Bh[2][4], Bl[2][4];
#pragma unroll
            for (int mt = 0; mt < 2; mt++) {
                uint32_t o = SWZ((uint32_t)((wm + mt * 16 + aRow) * 128 + ks * 32 + aKB));
                LDM4(Ah[mt], sb + stg + OFF_XH + o);
                LDM4(Al[mt], sb + stg + OFF_XL + o);
            }
#pragma unroll
            for (int p = 0; p < 2; p++) {
                uint32_t o = SWZ((uint32_t)((wn + p * 16 + bRow) * 128 + ks * 32 + bKB));
                LDM4(Bh[p], sb + stg + OFF_WH + o);
                LDM4(Bl[p], sb + stg + OFF_WL + o);
            }
#pragma unroll
            for (int mt = 0; mt < 2; mt++)
#pragma unroll
                for (int nt = 0; nt < 4; nt++) {
                    const int p = nt >> 1, r0 = (nt & 1) * 2;
                    MMA(acc1[mt][nt], Ah[mt], Bh[p][r0], Bh[p][r0 + 1]);
                    MMA(acc2[mt][nt], Al[mt], Bh[p][r0], Bh[p][r0 + 1]);
                    MMA(acc2[mt][nt], Ah[mt], Bl[p][r0], Bl[p][r0 + 1]);
                }
        }

        if (c + 1 < NCH) STORE_X(xr, nstg);
        CP_WAIT0();
        __syncthreads();
    }

    // ---- epilogue: combine accs -> logits smem [128][129] ----
    float* lg = (float*)smem;
    {
        const int r0 = lane >> 2;
        const int c0 = (lane & 3) * 2;
        const float inv = 1.0f / 2048.0f;
#pragma unroll
        for (int mt = 0; mt < 2; mt++)
#pragma unroll
            for (int nt = 0; nt < 4; nt++) {
                int row = wm + mt * 16 + r0;
                int col = wn + nt * 8 + c0;
                float v0 = acc1[mt][nt][0] + acc2[mt][nt][0] * inv;
                float v1 = acc1[mt][nt][1] + acc2[mt][nt][1] * inv;
                float v2 = acc1[mt][nt][2] + acc2[mt][nt][2] * inv;
                float v3 = acc1[mt][nt][3] + acc2[mt][nt][3] * inv;
                lg[(size_t)row * (NEXP + 1) + col]           = v0;
                lg[(size_t)row * (NEXP + 1) + col + 1]       = v1;
                lg[(size_t)(row + 8) * (NEXP + 1) + col]     = v2;
                lg[(size_t)(row + 8) * (NEXP + 1) + col + 1] = v3;
            }
    }
    __syncthreads();

    // ---- per-token softmax / top-8 / renorm (proven scan) ----
    if (tid < BM) {
        float* row = lg + (size_t)tid * (NEXP + 1);
        float m0 = row[0];
#pragma unroll 8
        for (int c = 1; c < NEXP; c++) {
            float v = row[c];
            if (v > m0) m0 = v;
        }
        int   ids[TOPK];
        float wts[TOPK];
        float sum = 0.0f;
#pragma unroll
        for (int kk = 0; kk < TOPK; kk++) {
            float best = -INFINITY;
            int   bi   = 0;
#pragma unroll 8
            for (int c = 0; c < NEXP; c++) {
                float v = row[c];
                if (v > best) { best = v; bi = c; }     // ties -> lowest index
            }
            row[bi] = -INFINITY;
            ids[kk] = bi;
            float e = expf(best - m0);
            wts[kk] = e;
            sum += e;
        }
        const int token = bm + tid;
        float* out_idx = out;
        float* out_wt  = out + (size_t)T * TOPK;
#pragma unroll
        for (int kk = 0; kk < TOPK; kk++) {
            out_idx[(size_t)token * TOPK + kk] = (float)ids[kk];
            out_wt [(size_t)token * TOPK + kk] = wts[kk] / sum;
        }
    }
}

extern "C" void kernel_launch(void* const* d_in, const int* in_sizes, int n_in,
                              void* d_out, int out_size)
{
    const float* x = (const float*)d_in[0];   // [4,4096,2048] fp32
    const float* w = (const float*)d_in[1];   // [128,2048]    fp32
    float* out = (float*)d_out;

    const int T = in_sizes[0] / HDIM;         // 16384

    prep_w_kernel<<<(NEXP * HDIM / 4) / 256, 256>>>(w);

    cudaFuncSetAttribute(gate_kernel,
                         cudaFuncAttributeMaxDynamicSharedMemorySize, SMEM_TOT);
    gate_kernel<<<T / BM, NTHR, SMEM_TOT>>>(x, out, T);
}

// round 8
// speedup vs baseline: 3.8124x; 1.0109x over previous
#include <cuda_runtime.h>
#include <cuda_fp16.h>
#include <math.h>
#include <stdint.h>

// Qwen3 MoE gate via 3-pass split-FP16 mma.sync (compute_103-safe: no tcgen05).
// logit = xh*wh + 2^-11*(xl_s*wh + xh*wl_s),  xl_s = fp16((x-xh)*2048), etc.
// R7: BM=64 / 256 thr / grid=256 / 2 CTAs per SM -> tensor-pipe overlap across
// CTAs hides the load/convert/sync bubbles that capped R6 at tensor=46.5%.
// Output: [idx f32 (T*8) | weights (T*8)].

#define HDIM 2048
#define NEXP 128
#define BM   64
#define BK   64                   // fp16 elements per K-chunk (128B rows)
#define NCH  (HDIM / BK)          // 32
#define NTHR 256
#define TOPK 8

#define XTILE_B  (BM * 128)       // 8KB  (64 rows x 128B)
#define WTILE_B  (NEXP * 128)     // 16KB (128 rows x 128B)
#define OFF_XH   0
#define OFF_XL   XTILE_B
#define OFF_WH   (2 * XTILE_B)
#define OFF_WL   (2 * XTILE_B + WTILE_B)
#define STAGE_B  (2 * XTILE_B + 2 * WTILE_B)   // 48KB per stage
#define SMEM_TOT (2 * STAGE_B)                 // 96KB (epilogue reuses: 64*129*4=33KB)

__device__ __half g_wh[NEXP * HDIM];
__device__ __half g_wl[NEXP * HDIM];

__device__ __forceinline__ uint32_t smem_u32(const void* p) {
    uint32_t a;
    asm("{ .reg .u64 t; cvta.to.shared.u64 t, %1; cvt.u32.u64 %0, t; }"
        : "=r"(a) : "l"(p));
    return a;
}

#define SWZ(o) ((o) ^ ((((uint32_t)(o)) >> 3) & 0x70))

#define CP16(dst, src) \
    asm volatile("cp.async.cg.shared.global [%0], [%1], 16;" \
                 :: "r"(dst), "l"(src))
#define CP_COMMIT() asm volatile("cp.async.commit_group;" ::: "memory")
#define CP_WAIT0()  asm volatile("cp.async.wait_group 0;" ::: "memory")

#define LDM4(R, a) \
    asm volatile("ldmatrix.sync.aligned.m8n8.x4.shared.b16 {%0,%1,%2,%3}, [%4];" \
                 : "=r"((R)[0]), "=r"((R)[1]), "=r"((R)[2]), "=r"((R)[3])      \
                 : "r"(a))

#define MMA(d, a, b0, b1) \
    asm volatile("mma.sync.aligned.m16n8k16.row.col.f32.f16.f16.f32 "          \
                 "{%0,%1,%2,%3}, {%4,%5,%6,%7}, {%8,%9}, {%0,%1,%2,%3};"       \
                 : "+f"((d)[0]), "+f"((d)[1]), "+f"((d)[2]), "+f"((d)[3])      \
                 : "r"((a)[0]), "r"((a)[1]), "r"((a)[2]), "r"((a)[3]),         \
                   "r"(b0), "r"(b1))

__device__ __forceinline__ uint32_t pack_h2(float a, float b) {
    __half2 h = __floats2half2_rn(a, b);
    return *(uint32_t*)&h;
}

// -------- prep: split W into fp16 hi + (lo * 2048) --------
__global__ void prep_w_kernel(const float* __restrict__ w) {
    int i = blockIdx.x * blockDim.x + threadIdx.x;      // float4 index
    float4 v = ((const float4*)w)[i];
    float hx = __half2float(__float2half_rn(v.x));
    float hy = __half2float(__float2half_rn(v.y));
    float hz = __half2float(__float2half_rn(v.z));
    float hw = __half2float(__float2half_rn(v.w));
    uint2 hi, lo;
    hi.x = pack_h2(hx, hy);
    hi.y = pack_h2(hz, hw);
    lo.x = pack_h2((v.x - hx) * 2048.0f, (v.y - hy) * 2048.0f);
    lo.y = pack_h2((v.z - hz) * 2048.0f, (v.w - hw) * 2048.0f);
    ((uint2*)g_wh)[i] = hi;
    ((uint2*)g_wl)[i] = lo;
}

// -------- main fused kernel --------
__global__ __launch_bounds__(NTHR, 2)
void gate_kernel(const float* __restrict__ x, float* __restrict__ out, int T)
{
    extern __shared__ char smem[];
    const uint32_t sb = smem_u32(smem);
    const int tid  = threadIdx.x;
    const int lane = tid & 31;
    const int wid  = tid >> 5;
    const int bm   = blockIdx.x * BM;

    // accumulators: [mt][nt][4]  (pass1, and combined correction passes)
    float acc1[2][4][4], acc2[2][4][4];
#pragma unroll
    for (int i = 0; i < 2; i++)
#pragma unroll
        for (int j = 0; j < 4; j++)
#pragma unroll
            for (int r = 0; r < 4; r++) { acc1[i][j][r] = 0.f; acc2[i][j][r] = 0.f; }

    // x loader: 64 rows x 16 float4 = 1024 float4; 4 per thread
    const int xrow[4] = { (tid + 0*NTHR) >> 4, (tid + 1*NTHR) >> 4,
                          (tid + 2*NTHR) >> 4, (tid + 3*NTHR) >> 4 };
    const int xq = tid & 15;
    const float* xg = x + (size_t)bm * HDIM;

    // W cp.async loader: 128 rows x 8 lines per operand; 4 lines/thread/operand
    const int wrow[4] = { (tid + 0*NTHR) >> 3, (tid + 1*NTHR) >> 3,
                          (tid + 2*NTHR) >> 3, (tid + 3*NTHR) >> 3 };
    const int ws = tid & 7;

    // warp tiling: 2(M) x 4(N) warps, warp tile 32(M) x 32(N)
    const int wm = (wid & 1) * 32;
    const int wn = (wid >> 1) * 32;
    // ldmatrix lane address components
    const int aRow = (lane & 7) + ((lane >> 3) & 1) * 8;   // + mt*16
    const int aKB  = ((lane >> 4) & 1) * 16;               // k-half bytes
    const int bRow = (lane & 7) + ((lane >> 4) & 1) * 8;   // + p*16
    const int bKB  = ((lane >> 3) & 1) * 16;

#define ISSUE_W(c, stg) do {                                                   \
    _Pragma("unroll")                                                          \
    for (int j = 0; j < 4; j++) {                                              \
        uint32_t o  = SWZ((uint32_t)(wrow[j] * 128 + ws * 16));                \
        const __half* sh = g_wh + (size_t)wrow[j] * HDIM + (c) * BK + ws * 8;  \
        const __half* sl = g_wl + (size_t)wrow[j] * HDIM + (c) * BK + ws * 8;  \
        CP16(sb + (stg) + OFF_WH + o, sh);                                     \
        CP16(sb + (stg) + OFF_WL + o, sl);                                     \
    }                                                                          \
    CP_COMMIT();                                                               \
} while (0)

#define LOAD_X(c, xr) do {                                                     \
    _Pragma("unroll")                                                          \
    for (int j = 0; j < 4; j++)                                                \
        xr[j] = *(const float4*)(xg + (size_t)xrow[j] * HDIM + (c) * BK + xq * 4); \
} while (0)

#define STORE_X(xr, stg) do {                                                  \
    _Pragma("unroll")                                                          \
    for (int j = 0; j < 4; j++) {                                              \
        float4 v = xr[j];                                                      \
        float hx = __half2float(__float2half_rn(v.x));                         \
        float hy = __half2float(__float2half_rn(v.y));                         \
        float hz = __half2float(__float2half_rn(v.z));                         \
        float hw = __half2float(__float2half_rn(v.w));                         \
        uint2 hi, lo;                                                          \
        hi.x = pack_h2(hx, hy);  hi.y = pack_h2(hz, hw);                       \
        lo.x = pack_h2((v.x - hx) * 2048.f, (v.y - hy) * 2048.f);              \
        lo.y = pack_h2((v.z - hz) * 2048.f, (v.w - hw) * 2048.f);              \
        uint32_t o = SWZ((uint32_t)(xrow[j] * 128 + xq * 8));                  \
        *(uint2*)(smem + (stg) + OFF_XH + o) = hi;                             \
        *(uint2*)(smem + (stg) + OFF_XL + o) = lo;                             \
    }                                                                          \
} while (0)

    // ---- prologue: chunk 0 into stage 0 ----
    {
        float4 xr[4];
        ISSUE_W(0, 0);
        LOAD_X(0, xr);
        STORE_X(xr, 0);
        CP_WAIT0();
        __syncthreads();
    }

    // ---- main loop ----
    for (int c = 0; c < NCH; c++) {
        const uint32_t stg  = (uint32_t)((c & 1) ? STAGE_B : 0);
        const uint32_t nstg = stg ^ STAGE_B;
        float4 xr[4];
        if (c + 1 < NCH) {
            ISSUE_W(c + 1, nstg);
            LOAD_X(c + 1, xr);
        }

        // MMA on stage `stg`
#pragma unroll
        for (int ks = 0; ks < 4; ks++) {
            uint32_t Ah[2][4], Al[2][4], Bh[2][4], Bl[2][4];
#pragma unroll
            for (int mt = 0; mt < 2; mt++) {
                uint32_t o = SWZ((uint32_t)((wm + mt * 16 + aRow) * 128 + ks * 32 + aKB));
                LDM4(Ah[mt], sb + stg + OFF_XH + o);
                LDM4(Al[mt], sb + stg + OFF_XL + o);
            }
#pragma unroll
            for (int p = 0; p < 2; p++) {
                uint32_t o = SWZ((uint32_t)((wn + p * 16 + bRow) * 128 + ks * 32 + bKB));
                LDM4(Bh[p], sb + stg + OFF_WH + o);
                LDM4(Bl[p], sb + stg + OFF_WL + o);
            }
#pragma unroll
            for (int mt = 0; mt < 2; mt++)
#pragma unroll
                for (int nt = 0; nt < 4; nt++) {
                    const int p = nt >> 1, r0 = (nt & 1) * 2;
                    MMA(acc1[mt][nt], Ah[mt], Bh[p][r0], Bh[p][r0 + 1]);
                    MMA(acc2[mt][nt], Al[mt], Bh[p][r0], Bh[p][r0 + 1]);
                    MMA(acc2[mt][nt], Ah[mt], Bl[p][r0], Bl[p][r0 + 1]);
                }
        }

        if (c + 1 < NCH) STORE_X(xr, nstg);
        CP_WAIT0();
        __syncthreads();
    }

    // ---- epilogue: combine accs -> logits smem [64][129] ----
    float* lg = (float*)smem;
    {
        const int r0 = lane >> 2;
        const int c0 = (lane & 3) * 2;
        const float inv = 1.0f / 2048.0f;
#pragma unroll
        for (int mt = 0; mt < 2; mt++)
#pragma unroll
            for (int nt = 0; nt < 4; nt++) {
                int row = wm + mt * 16 + r0;
                int col = wn + nt * 8 + c0;
                float v0 = acc1[mt][nt][0] + acc2[mt][nt][0] * inv;
                float v1 = acc1[mt][nt][1] + acc2[mt][nt][1] * inv;
                float v2 = acc1[mt][nt][2] + acc2[mt][nt][2] * inv;
                float v3 = acc1[mt][nt][3] + acc2[mt][nt][3] * inv;
                lg[(size_t)row * (NEXP + 1) + col]           = v0;
                lg[(size_t)row * (NEXP + 1) + col + 1]       = v1;
                lg[(size_t)(row + 8) * (NEXP + 1) + col]     = v2;
                lg[(size_t)(row + 8) * (NEXP + 1) + col + 1] = v3;
            }
    }
    __syncthreads();

    // ---- per-token softmax / top-8 / renorm (proven scan) ----
    if (tid < BM) {
        float* row = lg + (size_t)tid * (NEXP + 1);
        float m0 = row[0];
#pragma unroll 8
        for (int c = 1; c < NEXP; c++) {
            float v = row[c];
            if (v > m0) m0 = v;
        }
        int   ids[TOPK];
        float wts[TOPK];
        float sum = 0.0f;
#pragma unroll
        for (int kk = 0; kk < TOPK; kk++) {
            float best = -INFINITY;
            int   bi   = 0;
#pragma unroll 8
            for (int c = 0; c < NEXP; c++) {
                float v = row[c];
                if (v > best) { best = v; bi = c; }     // ties -> lowest index
            }
            row[bi] = -INFINITY;
            ids[kk] = bi;
            float e = expf(best - m0);
            wts[kk] = e;
            sum += e;
        }
        const int token = bm + tid;
        float* out_idx = out;
        float* out_wt  = out + (size_t)T * TOPK;
#pragma unroll
        for (int kk = 0; kk < TOPK; kk++) {
            out_idx[(size_t)token * TOPK + kk] = (float)ids[kk];
            out_wt [(size_t)token * TOPK + kk] = wts[kk] / sum;
        }
    }
}

extern "C" void kernel_launch(void* const* d_in, const int* in_sizes, int n_in,
                              void* d_out, int out_size)
{
    const float* x = (const float*)d_in[0];   // [4,4096,2048] fp32
    const float* w = (const float*)d_in[1];   // [128,2048]    fp32
    float* out = (float*)d_out;

    const int T = in_sizes[0] / HDIM;         // 16384

    prep_w_kernel<<<(NEXP * HDIM / 4) / 256, 256>>>(w);

    cudaFuncSetAttribute(gate_kernel,
                         cudaFuncAttributeMaxDynamicSharedMemorySize, SMEM_TOT);
    gate_kernel<<<T / BM, NTHR, SMEM_TOT>>>(x, out, T);
}

// round 9
// speedup vs baseline: 4.0242x; 1.0555x over previous
#include <cuda_runtime.h>
#include <cuda_fp16.h>
#include <math.h>
#include <stdint.h>

// Qwen3 MoE gate via split-FP16 mma.sync (compute_103-safe).
// logit = (xh*wh + xl*wh) [acc1] + 2^-11*(xh*wl_s) [acc2],  xl unscaled fp16.
// R8: warp tile 32x64 (4 warps, 2Mx2N, BM=64) -> 128B/MMA smem traffic
// (was 229), shared accumulator for the xl*wh pass. 2 CTAs/SM.
// Output: [idx f32 (T*8) | weights (T*8)].

#define HDIM 2048
#define NEXP 128
#define BM   64
#define BK   64                   // fp16 elements per K-chunk (128B rows)
#define NCH  (HDIM / BK)          // 32
#define NTHR 128
#define TOPK 8

#define XTILE_B  (BM * 128)       // 8KB  (64 rows x 128B)
#define WTILE_B  (NEXP * 128)     // 16KB (128 rows x 128B)
#define OFF_XH   0
#define OFF_XL   XTILE_B
#define OFF_WH   (2 * XTILE_B)
#define OFF_WL   (2 * XTILE_B + WTILE_B)
#define STAGE_B  (2 * XTILE_B + 2 * WTILE_B)   // 48KB per stage
#define SMEM_TOT (2 * STAGE_B)                 // 96KB (epilogue logits 33KB reuses)

__device__ __half g_wh[NEXP * HDIM];
__device__ __half g_wl[NEXP * HDIM];

__device__ __forceinline__ uint32_t smem_u32(const void* p) {
    uint32_t a;
    asm("{ .reg .u64 t; cvta.to.shared.u64 t, %1; cvt.u32.u64 %0, t; }"
        : "=r"(a) : "l"(p));
    return a;
}

#define SWZ(o) ((o) ^ ((((uint32_t)(o)) >> 3) & 0x70))

#define CP16(dst, src) \
    asm volatile("cp.async.cg.shared.global [%0], [%1], 16;" \
                 :: "r"(dst), "l"(src))
#define CP_COMMIT() asm volatile("cp.async.commit_group;" ::: "memory")
#define CP_WAIT0()  asm volatile("cp.async.wait_group 0;" ::: "memory")

#define LDM4(R, a) \
    asm volatile("ldmatrix.sync.aligned.m8n8.x4.shared.b16 {%0,%1,%2,%3}, [%4];" \
                 : "=r"((R)[0]), "=r"((R)[1]), "=r"((R)[2]), "=r"((R)[3])      \
                 : "r"(a))

#define MMA(d, a, b0, b1) \
    asm volatile("mma.sync.aligned.m16n8k16.row.col.f32.f16.f16.f32 "          \
                 "{%0,%1,%2,%3}, {%4,%5,%6,%7}, {%8,%9}, {%0,%1,%2,%3};"       \
                 : "+f"((d)[0]), "+f"((d)[1]), "+f"((d)[2]), "+f"((d)[3])      \
                 : "r"((a)[0]), "r"((a)[1]), "r"((a)[2]), "r"((a)[3]),         \
                   "r"(b0), "r"(b1))

__device__ __forceinline__ uint32_t pack_h2(float a, float b) {
    __half2 h = __floats2half2_rn(a, b);
    return *(uint32_t*)&h;
}

// -------- prep: split W into fp16 hi + (lo * 2048) --------
__global__ void prep_w_kernel(const float* __restrict__ w) {
    int i = blockIdx.x * blockDim.x + threadIdx.x;      // float4 index
    float4 v = ((const float4*)w)[i];
    float hx = __half2float(__float2half_rn(v.x));
    float hy = __half2float(__float2half_rn(v.y));
    float hz = __half2float(__float2half_rn(v.z));
    float hw = __half2float(__float2half_rn(v.w));
    uint2 hi, lo;
    hi.x = pack_h2(hx, hy);
    hi.y = pack_h2(hz, hw);
    lo.x = pack_h2((v.x - hx) * 2048.0f, (v.y - hy) * 2048.0f);
    lo.y = pack_h2((v.z - hz) * 2048.0f, (v.w - hw) * 2048.0f);
    ((uint2*)g_wh)[i] = hi;
    ((uint2*)g_wl)[i] = lo;
}

// -------- main fused kernel --------
__global__ __launch_bounds__(NTHR, 2)
void gate_kernel(const float* __restrict__ x, float* __restrict__ out, int T)
{
    extern __shared__ char smem[];
    const uint32_t sb = smem_u32(smem);
    const int tid  = threadIdx.x;
    const int lane = tid & 31;
    const int wid  = tid >> 5;
    const int bm   = blockIdx.x * BM;

    // accumulators: acc1 = xh*wh + xl*wh ; acc2 = xh*wl_s
    float acc1[2][8][4], acc2[2][8][4];
#pragma unroll
    for (int i = 0; i < 2; i++)
#pragma unroll
        for (int j = 0; j < 8; j++)
#pragma unroll
            for (int r = 0; r < 4; r++) { acc1[i][j][r] = 0.f; acc2[i][j][r] = 0.f; }

    // x loader: 64 rows x 16 float4 = 1024 float4; 8 per thread
    int xrow[8];
#pragma unroll
    for (int j = 0; j < 8; j++) xrow[j] = (tid + j * NTHR) >> 4;
    const int xq = tid & 15;
    const float* xg = x + (size_t)bm * HDIM;

    // W cp.async loader: 128 rows x 8 lines per operand; 8 lines/thread/operand
    int wrow[8];
#pragma unroll
    for (int j = 0; j < 8; j++) wrow[j] = (tid + j * NTHR) >> 3;
    const int ws = tid & 7;

    // warp tiling: 2(M) x 2(N) warps, warp tile 32(M) x 64(N)
    const int wm = (wid & 1) * 32;
    const int wn = (wid >> 1) * 64;
    // ldmatrix lane address components
    const int aRow = (lane & 7) + ((lane >> 3) & 1) * 8;   // + mt*16
    const int aKB  = ((lane >> 4) & 1) * 16;               // k-half bytes
    const int bRow = (lane & 7) + ((lane >> 4) & 1) * 8;   // + p*16
    const int bKB  = ((lane >> 3) & 1) * 16;

#define ISSUE_W(c, stg) do {                                                   \
    _Pragma("unroll")                                                          \
    for (int j = 0; j < 8; j++) {                                              \
        uint32_t o  = SWZ((uint32_t)(wrow[j] * 128 + ws * 16));                \
        const __half* sh = g_wh + (size_t)wrow[j] * HDIM + (c) * BK + ws * 8;  \
        const __half* sl = g_wl + (size_t)wrow[j] * HDIM + (c) * BK + ws * 8;  \
        CP16(sb + (stg) + OFF_WH + o, sh);                                     \
        CP16(sb + (stg) + OFF_WL + o, sl);                                     \
    }                                                                          \
    CP_COMMIT();                                                               \
} while (0)

#define LOAD_X(c, xr) do {                                                     \
    _Pragma("unroll")                                                          \
    for (int j = 0; j < 8; j++)                                                \
        xr[j] = *(const float4*)(xg + (size_t)xrow[j] * HDIM + (c) * BK + xq * 4); \
} while (0)

// xl stored UNSCALED (normal fp16 range ~1e-4..1e-3) -> shares acc with pass1
#define STORE_X(xr, stg) do {                                                  \
    _Pragma("unroll")                                                          \
    for (int j = 0; j < 8; j++) {                                              \
        float4 v = xr[j];                                                      \
        float hx = __half2float(__float2half_rn(v.x));                         \
        float hy = __half2float(__float2half_rn(v.y));                         \
        float hz = __half2float(__float2half_rn(v.z));                         \
        float hw = __half2float(__float2half_rn(v.w));                         \
        uint2 hi, lo;                                                          \
        hi.x = pack_h2(hx, hy);  hi.y = pack_h2(hz, hw);                       \
        lo.x = pack_h2(v.x - hx, v.y - hy);                                    \
        lo.y = pack_h2(v.z - hz, v.w - hw);                                    \
        uint32_t o = SWZ((uint32_t)(xrow[j] * 128 + xq * 8));                  \
        *(uint2*)(smem + (stg) + OFF_XH + o) = hi;                             \
        *(uint2*)(smem + (stg) + OFF_XL + o) = lo;                             \
    }                                                                          \
} while (0)

    // ---- prologue: chunk 0 into stage 0 ----
    {
        float4 xr[8];
        ISSUE_W(0, 0);
        LOAD_X(0, xr);
        STORE_X(xr, 0);
        CP_WAIT0();
        __syncthreads();
    }

    // ---- main loop ----
    for (int c = 0; c < NCH; c++) {
        const uint32_t stg  = (uint32_t)((c & 1) ? STAGE_B : 0);
        const uint32_t nstg = stg ^ STAGE_B;
        float4 xr[8];
        if (c + 1 < NCH) {
            ISSUE_W(c + 1, nstg);
            LOAD_X(c + 1, xr);
        }

        // MMA on stage `stg`
#pragma unroll
        for (int ks = 0; ks < 4; ks++) {
            uint32_t Ah[2][4], Al[2][4], Bh[4][4], Bl[4][4];
#pragma unroll
            for (int mt = 0; mt < 2; mt++) {
                uint32_t o = SWZ((uint32_t)((wm + mt * 16 + aRow) * 128 + ks * 32 + aKB));
                LDM4(Ah[mt], sb + stg + OFF_XH + o);
                LDM4(Al[mt], sb + stg + OFF_XL + o);
            }
#pragma unroll
            for (int p = 0; p < 4; p++) {
                uint32_t o = SWZ((uint32_t)((wn + p * 16 + bRow) * 128 + ks * 32 + bKB));
                LDM4(Bh[p], sb + stg + OFF_WH + o);
                LDM4(Bl[p], sb + stg + OFF_WL + o);
            }
#pragma unroll
            for (int mt = 0; mt < 2; mt++)
#pragma unroll
                for (int nt = 0; nt < 8; nt++) {
                    const int p = nt >> 1, r0 = (nt & 1) * 2;
                    MMA(acc1[mt][nt], Ah[mt], Bh[p][r0], Bh[p][r0 + 1]);
                    MMA(acc1[mt][nt], Al[mt], Bh[p][r0], Bh[p][r0 + 1]);
                    MMA(acc2[mt][nt], Ah[mt], Bl[p][r0], Bl[p][r0 + 1]);
                }
        }

        if (c + 1 < NCH) STORE_X(xr, nstg);
        CP_WAIT0();
        __syncthreads();
    }

    // ---- epilogue: combine accs -> logits smem [64][129] ----
    float* lg = (float*)smem;
    {
        const int r0 = lane >> 2;
        const int c0 = (lane & 3) * 2;
        const float inv = 1.0f / 2048.0f;
#pragma unroll
        for (int mt = 0; mt < 2; mt++)
#pragma unroll
            for (int nt = 0; nt < 8; nt++) {
                int row = wm + mt * 16 + r0;
                int col = wn + nt * 8 + c0;
                float v0 = acc1[mt][nt][0] + acc2[mt][nt][0] * inv;
                float v1 = acc1[mt][nt][1] + acc2[mt][nt][1] * inv;
                float v2 = acc1[mt][nt][2] + acc2[mt][nt][2] * inv;
                float v3 = acc1[mt][nt][3] + acc2[mt][nt][3] * inv;
                lg[(size_t)row * (NEXP + 1) + col]           = v0;
                lg[(size_t)row * (NEXP + 1) + col + 1]       = v1;
                lg[(size_t)(row + 8) * (NEXP + 1) + col]     = v2;
                lg[(size_t)(row + 8) * (NEXP + 1) + col + 1] = v3;
            }
    }
    __syncthreads();

    // ---- per-token softmax / top-8 / renorm (proven scan) ----
    if (tid < BM) {
        float* row = lg + (size_t)tid * (NEXP + 1);
        float m0 = row[0];
#pragma unroll 8
        for (int c = 1; c < NEXP; c++) {
            float v = row[c];
            if (v > m0) m0 = v;
        }
        int   ids[TOPK];
        float wts[TOPK];
        float sum = 0.0f;
#pragma unroll
        for (int kk = 0; kk < TOPK; kk++) {
            float best = -INFINITY;
            int   bi   = 0;
#pragma unroll 8
            for (int c = 0; c < NEXP; c++) {
                float v = row[c];
                if (v > best) { best = v; bi = c; }     // ties -> lowest index
            }
            row[bi] = -INFINITY;
            ids[kk] = bi;
            float e = expf(best - m0);
            wts[kk] = e;
            sum += e;
        }
        const int token = bm + tid;
        float* out_idx = out;
        float* out_wt  = out + (size_t)T * TOPK;
#pragma unroll
        for (int kk = 0; kk < TOPK; kk++) {
            out_idx[(size_t)token * TOPK + kk] = (float)ids[kk];
            out_wt [(size_t)token * TOPK + kk] = wts[kk] / sum;
        }
    }
}

extern "C" void kernel_launch(void* const* d_in, const int* in_sizes, int n_in,
                              void* d_out, int out_size)
{
    const float* x = (const float*)d_in[0];   // [4,4096,2048] fp32
    const float* w = (const float*)d_in[1];   // [128,2048]    fp32
    float* out = (float*)d_out;

    const int T = in_sizes[0] / HDIM;         // 16384

    prep_w_kernel<<<(NEXP * HDIM / 4) / 256, 256>>>(w);

    cudaFuncSetAttribute(gate_kernel,
                         cudaFuncAttributeMaxDynamicSharedMemorySize, SMEM_TOT);
    gate_kernel<<<T / BM, NTHR, SMEM_TOT>>>(x, out, T);
}

// round 10
// speedup vs baseline: 4.0329x; 1.0022x over previous
#include <cuda_runtime.h>
#include <cuda_fp16.h>
#include <math.h>
#include <stdint.h>

// Qwen3 MoE gate via split-FP16 mma.sync (compute_103-safe).
// logit = xh*wh [f32 acc] + 2^-11 * (xl_s*wh + xh*wl_s) [f16 acc, full-rate].
// R9: correction passes use f16 accumulation -> 4 half-rate tensor units per
// tile instead of 6 (f32-acc HMMA measured at half peak on sm_103a).
// Output: [idx f32 (T*8) | weights (T*8)].

#define HDIM 2048
#define NEXP 128
#define BM   64
#define BK   64                   // fp16 elements per K-chunk (128B rows)
#define NCH  (HDIM / BK)          // 32
#define NTHR 128
#define TOPK 8

#define XTILE_B  (BM * 128)       // 8KB  (64 rows x 128B)
#define WTILE_B  (NEXP * 128)     // 16KB (128 rows x 128B)
#define OFF_XH   0
#define OFF_XL   XTILE_B
#define OFF_WH   (2 * XTILE_B)
#define OFF_WL   (2 * XTILE_B + WTILE_B)
#define STAGE_B  (2 * XTILE_B + 2 * WTILE_B)   // 48KB per stage
#define SMEM_TOT (2 * STAGE_B)                 // 96KB (epilogue logits 33KB reuses)

__device__ __half g_wh[NEXP * HDIM];
__device__ __half g_wl[NEXP * HDIM];

__device__ __forceinline__ uint32_t smem_u32(const void* p) {
    uint32_t a;
    asm("{ .reg .u64 t; cvta.to.shared.u64 t, %1; cvt.u32.u64 %0, t; }"
        : "=r"(a) : "l"(p));
    return a;
}

#define SWZ(o) ((o) ^ ((((uint32_t)(o)) >> 3) & 0x70))

#define CP16(dst, src) \
    asm volatile("cp.async.cg.shared.global [%0], [%1], 16;" \
                 :: "r"(dst), "l"(src))
#define CP_COMMIT() asm volatile("cp.async.commit_group;" ::: "memory")
#define CP_WAIT0()  asm volatile("cp.async.wait_group 0;" ::: "memory")

#define LDM4(R, a) \
    asm volatile("ldmatrix.sync.aligned.m8n8.x4.shared.b16 {%0,%1,%2,%3}, [%4];" \
                 : "=r"((R)[0]), "=r"((R)[1]), "=r"((R)[2]), "=r"((R)[3])      \
                 : "r"(a))

// f32-accumulate MMA (half-rate on sm_103a legacy path)
#define MMA(d, a, b0, b1) \
    asm volatile("mma.sync.aligned.m16n8k16.row.col.f32.f16.f16.f32 "          \
                 "{%0,%1,%2,%3}, {%4,%5,%6,%7}, {%8,%9}, {%0,%1,%2,%3};"       \
                 : "+f"((d)[0]), "+f"((d)[1]), "+f"((d)[2]), "+f"((d)[3])      \
                 : "r"((a)[0]), "r"((a)[1]), "r"((a)[2]), "r"((a)[3]),         \
                   "r"(b0), "r"(b1))

// f16-accumulate MMA (full-rate) for the small correction terms
#define MMAH(d, a, b0, b1) \
    asm volatile("mma.sync.aligned.m16n8k16.row.col.f16.f16.f16.f16 "          \
                 "{%0,%1}, {%2,%3,%4,%5}, {%6,%7}, {%0,%1};"                   \
                 : "+r"((d)[0]), "+r"((d)[1])                                  \
                 : "r"((a)[0]), "r"((a)[1]), "r"((a)[2]), "r"((a)[3]),         \
                   "r"(b0), "r"(b1))

__device__ __forceinline__ uint32_t pack_h2(float a, float b) {
    __half2 h = __floats2half2_rn(a, b);
    return *(uint32_t*)&h;
}

// -------- prep: split W into fp16 hi + (lo * 2048) --------
__global__ void prep_w_kernel(const float* __restrict__ w) {
    int i = blockIdx.x * blockDim.x + threadIdx.x;      // float4 index
    float4 v = ((const float4*)w)[i];
    float hx = __half2float(__float2half_rn(v.x));
    float hy = __half2float(__float2half_rn(v.y));
    float hz = __half2float(__float2half_rn(v.z));
    float hw = __half2float(__float2half_rn(v.w));
    uint2 hi, lo;
    hi.x = pack_h2(hx, hy);
    hi.y = pack_h2(hz, hw);
    lo.x = pack_h2((v.x - hx) * 2048.0f, (v.y - hy) * 2048.0f);
    lo.y = pack_h2((v.z - hz) * 2048.0f, (v.w - hw) * 2048.0f);
    ((uint2*)g_wh)[i] = hi;
    ((uint2*)g_wl)[i] = lo;
}

// -------- main fused kernel --------
__global__ __launch_bounds__(NTHR, 2)
void gate_kernel(const float* __restrict__ x, float* __restrict__ out, int T)
{
    extern __shared__ char smem[];
    const uint32_t sb = smem_u32(smem);
    const int tid  = threadIdx.x;
    const int lane = tid & 31;
    const int wid  = tid >> 5;
    const int bm   = blockIdx.x * BM;

    // acc1 (f32): xh*wh.  acc2 (f16x2): xl_s*wh + xh*wl_s (scaled by 2048).
    float    acc1[2][8][4];
    uint32_t acc2[2][8][2];
#pragma unroll
    for (int i = 0; i < 2; i++)
#pragma unroll
        for (int j = 0; j < 8; j++) {
#pragma unroll
            for (int r = 0; r < 4; r++) acc1[i][j][r] = 0.f;
            acc2[i][j][0] = 0u; acc2[i][j][1] = 0u;
        }

    // x loader: 64 rows x 16 float4 = 1024 float4; 8 per thread
    int xrow[8];
#pragma unroll
    for (int j = 0; j < 8; j++) xrow[j] = (tid + j * NTHR) >> 4;
    const int xq = tid & 15;
    const float* xg = x + (size_t)bm * HDIM;

    // W cp.async loader: 128 rows x 8 lines per operand; 8 lines/thread/operand
    int wrow[8];
#pragma unroll
    for (int j = 0; j < 8; j++) wrow[j] = (tid + j * NTHR) >> 3;
    const int ws = tid & 7;

    // warp tiling: 2(M) x 2(N) warps, warp tile 32(M) x 64(N)
    const int wm = (wid & 1) * 32;
    const int wn = (wid >> 1) * 64;
    // ldmatrix lane address components
    const int aRow = (lane & 7) + ((lane >> 3) & 1) * 8;   // + mt*16
    const int aKB  = ((lane >> 4) & 1) * 16;               // k-half bytes
    const int bRow = (lane & 7) + ((lane >> 4) & 1) * 8;   // + p*16
    const int bKB  = ((lane >> 3) & 1) * 16;

#define ISSUE_W(c, stg) do {                                                   \
    _Pragma("unroll")                                                          \
    for (int j = 0; j < 8; j++) {                                              \
        uint32_t o  = SWZ((uint32_t)(wrow[j] * 128 + ws * 16));                \
        const __half* sh = g_wh + (size_t)wrow[j] * HDIM + (c) * BK + ws * 8;  \
        const __half* sl = g_wl + (size_t)wrow[j] * HDIM + (c) * BK + ws * 8;  \
        CP16(sb + (stg) + OFF_WH + o, sh);                                     \
        CP16(sb + (stg) + OFF_WL + o, sl);                                     \
    }                                                                          \
    CP_COMMIT();                                                               \
} while (0)

#define LOAD_X(c, xr) do {                                                     \
    _Pragma("unroll")                                                          \
    for (int j = 0; j < 8; j++)                                                \
        xr[j] = *(const float4*)(xg + (size_t)xrow[j] * HDIM + (c) * BK + xq * 4); \
} while (0)

// xl stored scaled by 2048 (keeps f16-acc magnitudes in normal range)
#define STORE_X(xr, stg) do {                                                  \
    _Pragma("unroll")                                                          \
    for (int j = 0; j < 8; j++) {                                              \
        float4 v = xr[j];                                                      \
        float hx = __half2float(__float2half_rn(v.x));                         \
        float hy = __half2float(__float2half_rn(v.y));                         \
        float hz = __half2float(__float2half_rn(v.z));                         \
        float hw = __half2float(__float2half_rn(v.w));                         \
        uint2 hi, lo;                                                          \
        hi.x = pack_h2(hx, hy);  hi.y = pack_h2(hz, hw);                       \
        lo.x = pack_h2((v.x - hx) * 2048.f, (v.y - hy) * 2048.f);              \
        lo.y = pack_h2((v.z - hz) * 2048.f, (v.w - hw) * 2048.f);              \
        uint32_t o = SWZ((uint32_t)(xrow[j] * 128 + xq * 8));                  \
        *(uint2*)(smem + (stg) + OFF_XH + o) = hi;                             \
        *(uint2*)(smem + (stg) + OFF_XL + o) = lo;                             \
    }                                                                          \
} while (0)

    // ---- prologue: chunk 0 into stage 0 ----
    {
        float4 xr[8];
        ISSUE_W(0, 0);
        LOAD_X(0, xr);
        STORE_X(xr, 0);
        CP_WAIT0();
        __syncthreads();
    }

    // ---- main loop ----
    for (int c = 0; c < NCH; c++) {
        const uint32_t stg  = (uint32_t)((c & 1) ? STAGE_B : 0);
        const uint32_t nstg = stg ^ STAGE_B;
        float4 xr[8];
        if (c + 1 < NCH) {
            ISSUE_W(c + 1, nstg);
            LOAD_X(c + 1, xr);
        }

        // MMA on stage `stg`
#pragma unroll
        for (int ks = 0; ks < 4; ks++) {
            uint32_t Ah[2][4], Al[2][4], Bh[4][4], Bl[4][4];
#pragma unroll
            for (int mt = 0; mt < 2; mt++) {
                uint32_t o = SWZ((uint32_t)((wm + mt * 16 + aRow) * 128 + ks * 32 + aKB));
                LDM4(Ah[mt], sb + stg + OFF_XH + o);
                LDM4(Al[mt], sb + stg + OFF_XL + o);
            }
#pragma unroll
            for (int p = 0; p < 4; p++) {
                uint32_t o = SWZ((uint32_t)((wn + p * 16 + bRow) * 128 + ks * 32 + bKB));
                LDM4(Bh[p], sb + stg + OFF_WH + o);
                LDM4(Bl[p], sb + stg + OFF_WL + o);
            }
#pragma unroll
            for (int mt = 0; mt < 2; mt++)
#pragma unroll
                for (int nt = 0; nt < 8; nt++) {
                    const int p = nt >> 1, r0 = (nt & 1) * 2;
                    MMA (acc1[mt][nt], Ah[mt], Bh[p][r0], Bh[p][r0 + 1]);
                    MMAH(acc2[mt][nt], Al[mt], Bh[p][r0], Bh[p][r0 + 1]);
                    MMAH(acc2[mt][nt], Ah[mt], Bl[p][r0], Bl[p][r0 + 1]);
                }
        }

        if (c + 1 < NCH) STORE_X(xr, nstg);
        CP_WAIT0();
        __syncthreads();
    }

    // ---- epilogue: combine accs -> logits smem [64][129] ----
    float* lg = (float*)smem;
    {
        const int r0 = lane >> 2;
        const int c0 = (lane & 3) * 2;
        const float inv = 1.0f / 2048.0f;
#pragma unroll
        for (int mt = 0; mt < 2; mt++)
#pragma unroll
            for (int nt = 0; nt < 8; nt++) {
                int row = wm + mt * 16 + r0;
                int col = wn + nt * 8 + c0;
                __half2 h01 = *(__half2*)&acc2[mt][nt][0];   // c0, c1
                __half2 h23 = *(__half2*)&acc2[mt][nt][1];   // c2, c3
                float v0 = acc1[mt][nt][0] + __low2float (h01) * inv;
                float v1 = acc1[mt][nt][1] + __high2float(h01) * inv;
                float v2 = acc1[mt][nt][2] + __low2float (h23) * inv;
                float v3 = acc1[mt][nt][3] + __high2float(h23) * inv;
                lg[(size_t)row * (NEXP + 1) + col]           = v0;
                lg[(size_t)row * (NEXP + 1) + col + 1]       = v1;
                lg[(size_t)(row + 8) * (NEXP + 1) + col]     = v2;
                lg[(size_t)(row + 8) * (NEXP + 1) + col + 1] = v3;
            }
    }
    __syncthreads();

    // ---- per-token softmax / top-8 / renorm (proven scan) ----
    if (tid < BM) {
        float* row = lg + (size_t)tid * (NEXP + 1);
        float m0 = row[0];
#pragma unroll 8
        for (int c = 1; c < NEXP; c++) {
            float v = row[c];
            if (v > m0) m0 = v;
        }
        int   ids[TOPK];
        float wts[TOPK];
        float sum = 0.0f;
#pragma unroll
        for (int kk = 0; kk < TOPK; kk++) {
            float best = -INFINITY;
            int   bi   = 0;
#pragma unroll 8
            for (int c = 0; c < NEXP; c++) {
                float v = row[c];
                if (v > best) { best = v; bi = c; }     // ties -> lowest index
            }
            row[bi] = -INFINITY;
            ids[kk] = bi;
            float e = expf(best - m0);
            wts[kk] = e;
            sum += e;
        }
        const int token = bm + tid;
        float* out_idx = out;
        float* out_wt  = out + (size_t)T * TOPK;
#pragma unroll
        for (int kk = 0; kk < TOPK; kk++) {
            out_idx[(size_t)token * TOPK + kk] = (float)ids[kk];
            out_wt [(size_t)token * TOPK + kk] = wts[kk] / sum;
        }
    }
}

extern "C" void kernel_launch(void* const* d_in, const int* in_sizes, int n_in,
                              void* d_out, int out_size)
{
    const float* x = (const float*)d_in[0];   // [4,4096,2048] fp32
    const float* w = (const float*)d_in[1];   // [128,2048]    fp32
    float* out = (float*)d_out;

    const int T = in_sizes[0] / HDIM;         // 16384

    prep_w_kernel<<<(NEXP * HDIM / 4) / 256, 256>>>(w);

    cudaFuncSetAttribute(gate_kernel,
                         cudaFuncAttributeMaxDynamicSharedMemorySize, SMEM_TOT);
    gate_kernel<<<T / BM, NTHR, SMEM_TOT>>>(x, out, T);
}